// round 3
// baseline (speedup 1.0000x reference)
#include <cuda_runtime.h>
#include <cstdint>
#include <cstddef>

// Sinkhorn distance, N=M=4096, D=2, P=1, eps=0.1, 50 iterations.
// Outputs (concatenated, float32): [cost (1)] [pi (4096*4096)] [C (4096*4096)]
//
// Key identities used:
//   u_new_i = eps*log_mu - eps * lse_j((v_j - C_ij)/eps)        (u_i cancels)
//   v_new_j = eps*log_nu - eps * lse_i((u_i - C_ij)/eps)        (v_j cancels)
// Work in log2 units: pre-scale x,y,potentials by K = log2(e)/eps so the
// inner loop is FADD/FMNMX + one ex2.approx per matrix entry.

#define NPTS    4096
#define THREADS 256
#define JPT     16          // 4096 / 256 j-entries per thread
#define RPB     4           // rows per block in the update kernel
#define NBLK    (NPTS / RPB)
#define NITER   50

#define KSCALE  14.426950408889634f      // log2(e) / eps
#define EPS_LN2 0.069314718055994531f    // eps * ln(2)
#define CONST_A (-0.8317725207f)         // eps * ln(1/4096 + 1e-8)

// Scratch (no allocations allowed -> __device__ globals)
__device__ float g_u[NPTS], g_v[NPTS];
__device__ float g_xs0[NPTS], g_xs1[NPTS];   // x coords * KSCALE
__device__ float g_ys0[NPTS], g_ys1[NPTS];   // y coords * KSCALE
__device__ float g_part[NPTS];               // per-row cost partials

__device__ __forceinline__ float ex2f(float x) {
    float r; asm("ex2.approx.ftz.f32 %0, %1;" : "=f"(r) : "f"(x)); return r;
}
__device__ __forceinline__ float lg2f(float x) {
    float r; asm("lg2.approx.f32 %0, %1;" : "=f"(r) : "f"(x)); return r;
}

__global__ void init_kernel(const float2* __restrict__ x,
                            const float2* __restrict__ y) {
    int i = blockIdx.x * blockDim.x + threadIdx.x;
    float2 xi = x[i];
    float2 yi = y[i];
    g_u[i] = 0.0f;
    g_v[i] = 0.0f;
    g_xs0[i] = xi.x * KSCALE;
    g_xs1[i] = xi.y * KSCALE;
    g_ys0[i] = yi.x * KSCALE;
    g_ys1[i] = yi.y * KSCALE;
}

// One half-iteration. dir==0: update u (rows = x, reduce over y with v).
//                     dir==1: update v (rows = y, reduce over x with u).
__global__ __launch_bounds__(THREADS) void update_kernel(int dir) {
    const float* __restrict__ xs0 = dir ? g_ys0 : g_xs0;
    const float* __restrict__ xs1 = dir ? g_ys1 : g_xs1;
    const float* __restrict__ ys0 = dir ? g_xs0 : g_ys0;
    const float* __restrict__ ys1 = dir ? g_xs1 : g_ys1;
    const float* __restrict__ w   = dir ? g_u   : g_v;
    float*       __restrict__ out = dir ? g_v   : g_u;

    __shared__ float red[THREADS / 32];
    __shared__ float bcast;

    const int tid  = threadIdx.x;
    const int lane = tid & 31;
    const int wid  = tid >> 5;

    // Load this thread's slice of the "other" side into registers once;
    // reused across RPB rows.
    float y0[JPT], y1[JPT], wv[JPT];
#pragma unroll
    for (int k = 0; k < JPT; k++) {
        int j = tid + k * THREADS;
        y0[k] = ys0[j];
        y1[k] = ys1[j];
        wv[k] = w[j] * KSCALE;     // potential in log2/eps units
    }

    for (int r = 0; r < RPB; r++) {
        int i = blockIdx.x * RPB + r;
        float X0 = xs0[i];
        float X1 = xs1[i];

        // ---- pass 1: t_j = wv_j - |X0-y0_j| - |X1-y1_j|, track max ----
        float t[JPT];
        float m = -3.4e38f;
#pragma unroll
        for (int k = 0; k < JPT; k++) {
            float d0 = X0 - y0[k];
            float d1 = X1 - y1[k];
            float tk = wv[k] - fabsf(d0) - fabsf(d1);
            t[k] = tk;
            m = fmaxf(m, tk);
        }
#pragma unroll
        for (int o = 16; o; o >>= 1)
            m = fmaxf(m, __shfl_xor_sync(0xffffffffu, m, o));
        if (lane == 0) red[wid] = m;
        __syncthreads();
        if (tid == 0) {
            float bm = red[0];
#pragma unroll
            for (int q = 1; q < THREADS / 32; q++) bm = fmaxf(bm, red[q]);
            bcast = bm;
        }
        __syncthreads();
        m = bcast;

        // ---- pass 2: S = sum 2^(t_j - m) ----
        float s = 0.0f;
#pragma unroll
        for (int k = 0; k < JPT; k++)
            s += ex2f(t[k] - m);
#pragma unroll
        for (int o = 16; o; o >>= 1)
            s += __shfl_xor_sync(0xffffffffu, s, o);
        if (lane == 0) red[wid] = s;
        __syncthreads();
        if (tid == 0) {
            float ss = 0.0f;
#pragma unroll
            for (int q = 0; q < THREADS / 32; q++) ss += red[q];
            // u_new = eps*log_mu - eps*ln2*(m + log2(S))
            out[i] = CONST_A - EPS_LN2 * (m + lg2f(ss));
        }
        __syncthreads();   // protect red/bcast for next row
    }
}

// Write pi and C, accumulate per-row cost partials (deterministic order).
__global__ __launch_bounds__(THREADS) void finalize_kernel(
    const float2* __restrict__ x, const float2* __restrict__ y,
    float* __restrict__ out) {
    __shared__ float red[THREADS / 32];
    const int i = blockIdx.x;
    const int tid = threadIdx.x;

    float2 xi = x[i];
    float ui = g_u[i];
    float* __restrict__ pi_out = out + 1;
    float* __restrict__ c_out  = out + 1 + (size_t)NPTS * NPTS;
    const size_t base = (size_t)i * NPTS;

    float acc = 0.0f;
#pragma unroll
    for (int k = 0; k < JPT; k++) {
        int j = tid + k * THREADS;
        float2 yj = y[j];
        float c = fabsf(xi.x - yj.x) + fabsf(xi.y - yj.y);
        float p = ex2f((ui + g_v[j] - c) * KSCALE);
        pi_out[base + j] = p;
        c_out[base + j]  = c;
        acc += p * c;
    }
#pragma unroll
    for (int o = 16; o; o >>= 1)
        acc += __shfl_xor_sync(0xffffffffu, acc, o);
    if ((tid & 31) == 0) red[tid >> 5] = acc;
    __syncthreads();
    if (tid == 0) {
        float s = 0.0f;
#pragma unroll
        for (int q = 0; q < THREADS / 32; q++) s += red[q];
        g_part[i] = s;
    }
}

__global__ __launch_bounds__(THREADS) void cost_reduce(float* __restrict__ out) {
    __shared__ float red[THREADS / 32];
    const int tid = threadIdx.x;
    float s = 0.0f;
    for (int k = tid; k < NPTS; k += THREADS) s += g_part[k];
#pragma unroll
    for (int o = 16; o; o >>= 1)
        s += __shfl_xor_sync(0xffffffffu, s, o);
    if ((tid & 31) == 0) red[tid >> 5] = s;
    __syncthreads();
    if (tid == 0) {
        float t = 0.0f;
#pragma unroll
        for (int q = 0; q < THREADS / 32; q++) t += red[q];
        out[0] = t;   // P = 1 -> cost^(1/P) == cost
    }
}

extern "C" void kernel_launch(void* const* d_in, const int* in_sizes, int n_in,
                              void* d_out, int out_size) {
    const float2* x = (const float2*)d_in[0];
    const float2* y = (const float2*)d_in[1];
    float* out = (float*)d_out;

    init_kernel<<<NPTS / THREADS, THREADS>>>(x, y);
    for (int it = 0; it < NITER; ++it) {
        update_kernel<<<NBLK, THREADS>>>(0);   // u-update (uses v)
        update_kernel<<<NBLK, THREADS>>>(1);   // v-update (uses new u)
    }
    finalize_kernel<<<NPTS, THREADS>>>(x, y, out);
    cost_reduce<<<1, THREADS>>>(out);
    (void)in_sizes; (void)n_in; (void)out_size;
}

// round 6
// speedup vs baseline: 1.4318x; 1.4318x over previous
#include <cuda_runtime.h>
#include <cstdint>
#include <cstddef>

// Sinkhorn distance, N=M=4096, D=2, P=1, eps=0.1, 50 iterations.
// Outputs (concatenated, float32): [cost (1)] [pi (4096*4096)] [C (4096*4096)]
//
// u_new_i = eps*log_mu - eps*lse_j((v_j - C_ij)/eps)   (the +u_i term cancels)
// Work in log2 units (scale by K = log2(e)/eps): inner loop is packed f32x2
// adds + sign-trick abs + one ex2.approx per entry. No max-shift pass: row
// max of t is provably >> -126 (nearest-neighbor distance bound), so direct
// sum of 2^t is fp32-safe and matches the shifted version to accumulation
// precision.

#define NPTS    4096
#define THREADS 512
#define PAIRS   4            // 512 thr * 4 pairs * 2 = 4096 j-entries
#define GRID    296          // 2 blocks/SM * 148 SMs, single wave
#define MAXROWS 14           // ceil(4096/296)
#define NITER   50

#define KSCALE  14.426950408889634f      // log2(e) / eps
#define EPS_LN2 0.069314718055994531f    // eps * ln(2)
#define CONST_A (-0.8317725207f)         // eps * ln(1/4096 + 1e-8)
#define SIGNS   0x8000000080000000ULL

// Scratch (no allocations allowed -> __device__ globals)
__device__ __align__(16) float g_u[NPTS], g_v[NPTS];
__device__ __align__(16) float g_xs0[NPTS], g_xs1[NPTS];   // x coords * KSCALE
__device__ __align__(16) float g_ys0[NPTS], g_ys1[NPTS];   // y coords * KSCALE
__device__ float g_part[NPTS];                             // per-row cost partials

__device__ __forceinline__ float ex2f(float x) {
    float r; asm("ex2.approx.ftz.f32 %0, %1;" : "=f"(r) : "f"(x)); return r;
}
__device__ __forceinline__ float lg2f(float x) {
    float r; asm("lg2.approx.f32 %0, %1;" : "=f"(r) : "f"(x)); return r;
}
__device__ __forceinline__ unsigned long long packf2(float lo, float hi) {
    unsigned long long r;
    asm("mov.b64 %0, {%1, %2};" : "=l"(r) : "f"(lo), "f"(hi));
    return r;
}
__device__ __forceinline__ void unpackf2(unsigned long long v, float& lo, float& hi) {
    asm("mov.b64 {%0, %1}, %2;" : "=f"(lo), "=f"(hi) : "l"(v));
}
__device__ __forceinline__ unsigned long long addx2(unsigned long long a,
                                                    unsigned long long b) {
    unsigned long long r;
    asm("add.rn.f32x2 %0, %1, %2;" : "=l"(r) : "l"(a), "l"(b));
    return r;
}

__global__ void init_kernel(const float2* __restrict__ x,
                            const float2* __restrict__ y) {
    int i = blockIdx.x * blockDim.x + threadIdx.x;
    float2 xi = x[i];
    float2 yi = y[i];
    g_u[i] = 0.0f;
    g_v[i] = 0.0f;
    g_xs0[i] = xi.x * KSCALE;
    g_xs1[i] = xi.y * KSCALE;
    g_ys0[i] = yi.x * KSCALE;
    g_ys1[i] = yi.y * KSCALE;
}

// One half-iteration. dir==0: update u (rows = x, reduce over y with v).
//                     dir==1: update v (rows = y, reduce over x with u).
__global__ __launch_bounds__(THREADS, 2) void update_kernel(int dir) {
    const float*  __restrict__ xs0 = dir ? g_ys0 : g_xs0;
    const float*  __restrict__ xs1 = dir ? g_ys1 : g_xs1;
    const float2* __restrict__ yv0 = (const float2*)(dir ? g_xs0 : g_ys0);
    const float2* __restrict__ yv1 = (const float2*)(dir ? g_xs1 : g_ys1);
    const float2* __restrict__ wv2 = (const float2*)(dir ? g_u : g_v);
    float*        __restrict__ out = dir ? g_v : g_u;

    __shared__ float part[MAXROWS][THREADS / 32];

    const int tid  = threadIdx.x;
    const int lane = tid & 31;
    const int wid  = tid >> 5;

    // Cache this thread's slice of the reduce-side in registers (negated y,
    // scaled potential), packed as f32x2 pairs. Reused for all rows.
    unsigned long long ny0[PAIRS], ny1[PAIRS], wvp[PAIRS];
#pragma unroll
    for (int k = 0; k < PAIRS; k++) {
        int idx = tid + k * THREADS;           // pair index -> j = 2*idx, 2*idx+1
        float2 a = yv0[idx];
        float2 b = yv1[idx];
        float2 w = wv2[idx];
        ny0[k] = packf2(-a.x, -a.y);
        ny1[k] = packf2(-b.x, -b.y);
        wvp[k] = packf2(w.x * KSCALE, w.y * KSCALE);
    }

    int nrows = 0;
    for (int i = blockIdx.x; i < NPTS; i += GRID) {
        float x0 = xs0[i];
        float x1 = xs1[i];
        unsigned long long X0p = packf2(x0, x0);
        unsigned long long X1p = packf2(x1, x1);

        float a0 = 0.0f, a1 = 0.0f;
#pragma unroll
        for (int k = 0; k < PAIRS; k++) {
            unsigned long long d0 = addx2(X0p, ny0[k]);       // x0 - y0 (x2)
            unsigned long long d1 = addx2(X1p, ny1[k]);       // x1 - y1 (x2)
            // -|d| == d with sign bit forced (per 32-bit half)
            unsigned long long t =
                addx2(addx2(wvp[k], d0 | SIGNS), d1 | SIGNS); // wv - |d0| - |d1|
            float tl, th;
            unpackf2(t, tl, th);
            a0 += ex2f(tl);
            a1 += ex2f(th);
        }
        float s = a0 + a1;
#pragma unroll
        for (int o = 16; o; o >>= 1)
            s += __shfl_xor_sync(0xffffffffu, s, o);
        if (lane == 0) part[nrows][wid] = s;
        nrows++;                                // identical across all threads
    }

    __syncthreads();                            // single barrier per launch
    for (int rr = tid; rr < nrows; rr += THREADS) {
        float ss = 0.0f;
#pragma unroll
        for (int q = 0; q < THREADS / 32; q++) ss += part[rr][q];
        out[blockIdx.x + rr * GRID] = CONST_A - EPS_LN2 * lg2f(ss);
    }
}

// Write pi and C, accumulate per-row cost partials (deterministic order).
#define FTHREADS 256
#define FJPT     16
__global__ __launch_bounds__(FTHREADS) void finalize_kernel(
    const float2* __restrict__ x, const float2* __restrict__ y,
    float* __restrict__ out) {
    __shared__ float red[FTHREADS / 32];
    const int i = blockIdx.x;
    const int tid = threadIdx.x;

    float2 xi = x[i];
    float ui = g_u[i];
    float* __restrict__ pi_out = out + 1;
    float* __restrict__ c_out  = out + 1 + (size_t)NPTS * NPTS;
    const size_t base = (size_t)i * NPTS;

    float acc = 0.0f;
#pragma unroll
    for (int k = 0; k < FJPT; k++) {
        int j = tid + k * FTHREADS;
        float2 yj = y[j];
        float c = fabsf(xi.x - yj.x) + fabsf(xi.y - yj.y);
        float p = ex2f((ui + g_v[j] - c) * KSCALE);
        pi_out[base + j] = p;
        c_out[base + j]  = c;
        acc += p * c;
    }
#pragma unroll
    for (int o = 16; o; o >>= 1)
        acc += __shfl_xor_sync(0xffffffffu, acc, o);
    if ((tid & 31) == 0) red[tid >> 5] = acc;
    __syncthreads();
    if (tid == 0) {
        float s = 0.0f;
#pragma unroll
        for (int q = 0; q < FTHREADS / 32; q++) s += red[q];
        g_part[i] = s;
    }
}

__global__ __launch_bounds__(FTHREADS) void cost_reduce(float* __restrict__ out) {
    __shared__ float red[FTHREADS / 32];
    const int tid = threadIdx.x;
    float s = 0.0f;
    for (int k = tid; k < NPTS; k += FTHREADS) s += g_part[k];
#pragma unroll
    for (int o = 16; o; o >>= 1)
        s += __shfl_xor_sync(0xffffffffu, s, o);
    if ((tid & 31) == 0) red[tid >> 5] = s;
    __syncthreads();
    if (tid == 0) {
        float t = 0.0f;
#pragma unroll
        for (int q = 0; q < FTHREADS / 32; q++) t += red[q];
        out[0] = t;   // P = 1 -> cost^(1/P) == cost
    }
}

extern "C" void kernel_launch(void* const* d_in, const int* in_sizes, int n_in,
                              void* d_out, int out_size) {
    const float2* x = (const float2*)d_in[0];
    const float2* y = (const float2*)d_in[1];
    float* out = (float*)d_out;

    init_kernel<<<NPTS / 256, 256>>>(x, y);
    for (int it = 0; it < NITER; ++it) {
        update_kernel<<<GRID, THREADS>>>(0);   // u-update (uses v)
        update_kernel<<<GRID, THREADS>>>(1);   // v-update (uses new u)
    }
    finalize_kernel<<<NPTS, FTHREADS>>>(x, y, out);
    cost_reduce<<<1, FTHREADS>>>(out);
    (void)in_sizes; (void)n_in; (void)out_size;
}

// round 7
// speedup vs baseline: 1.5330x; 1.0707x over previous
#include <cuda_runtime.h>
#include <cstdint>
#include <cstddef>

// Sinkhorn distance, N=M=4096, D=2, P=1, eps=0.1, 50 iterations.
// Outputs (concatenated, float32): [cost (1)] [pi (4096*4096)] [C (4096*4096)]
//
// u_new_i = eps*log_mu - eps*lse_j((v_j - C_ij)/eps)   (the +u_i term cancels)
//
// This version fuses all 100 half-iterations into ONE persistent kernel
// (grid=296 = 2 blocks/SM, co-residency guaranteed by __launch_bounds__(512,2))
// with a software grid barrier between half-iterations.
//
// Math: rotated coords p=(x0+x1)*K, q=(x0-x1)*K with K=log2(e)/eps give
//   t_ij = w_j*K - max(|p_i-p_j|, |q_i-q_j|)         (log2 units)
// and the row update is  out_i = A - eps*ln2*log2(sum_j 2^t_ij).
// No max-shift: row max of t is bounded far above fp32 underflow
// (nearest-neighbor argument), validated in prior rounds (rel_err ~1e-6).

#define NPTS    4096
#define THREADS 512
#define PAIRS   4            // 512 thr * 4 pairs * 2 = 4096 j-entries
#define GRID    296          // 2 blocks/SM * 148 SMs, single wave (co-resident)
#define MAXROWS 14           // ceil(4096/296)
#define NITER   50
#define NPHASE  (2 * NITER)

#define KSCALE  14.426950408889634f      // log2(e) / eps
#define EPS_LN2 0.069314718055994531f    // eps * ln(2)
#define CONST_A (-0.8317725207f)         // eps * ln(1/4096 + 1e-8)

// Scratch (no allocations allowed -> __device__ globals)
__device__ __align__(16) float g_pr[2][NPTS];   // rotated+scaled: side0=x, side1=y
__device__ __align__(16) float g_qr[2][NPTS];
__device__ __align__(16) float g_u[NPTS], g_v[NPTS];
__device__ float g_part[NPTS];
__device__ unsigned g_arrive;
__device__ volatile unsigned g_gen;

__device__ __forceinline__ float ex2f(float x) {
    float r; asm("ex2.approx.ftz.f32 %0, %1;" : "=f"(r) : "f"(x)); return r;
}
__device__ __forceinline__ float lg2f(float x) {
    float r; asm("lg2.approx.f32 %0, %1;" : "=f"(r) : "f"(x)); return r;
}
__device__ __forceinline__ unsigned long long packf2(float lo, float hi) {
    unsigned long long r;
    asm("mov.b64 %0, {%1, %2};" : "=l"(r) : "f"(lo), "f"(hi));
    return r;
}
__device__ __forceinline__ void unpackf2(unsigned long long v, float& lo, float& hi) {
    asm("mov.b64 {%0, %1}, %2;" : "=f"(lo), "=f"(hi) : "l"(v));
}
__device__ __forceinline__ unsigned long long addx2(unsigned long long a,
                                                    unsigned long long b) {
    unsigned long long r;
    asm("add.rn.f32x2 %0, %1, %2;" : "=l"(r) : "l"(a), "l"(b));
    return r;
}

__global__ void init_kernel(const float2* __restrict__ x,
                            const float2* __restrict__ y) {
    int i = blockIdx.x * blockDim.x + threadIdx.x;
    if (i == 0) { g_arrive = 0u; g_gen = 0u; }     // reset barrier (graph replays!)
    float2 xi = x[i];
    float2 yi = y[i];
    g_u[i] = 0.0f;
    g_v[i] = 0.0f;
    g_pr[0][i] = (xi.x + xi.y) * KSCALE;
    g_qr[0][i] = (xi.x - xi.y) * KSCALE;
    g_pr[1][i] = (yi.x + yi.y) * KSCALE;
    g_qr[1][i] = (yi.x - yi.y) * KSCALE;
}

// Classic multi-block barrier: release via monotone generation counter.
__device__ __forceinline__ void grid_barrier(int b) {
    __syncthreads();
    if (threadIdx.x == 0) {
        __threadfence();
        unsigned t = atomicAdd(&g_arrive, 1u);
        unsigned target = (unsigned)(b + 1) * (unsigned)GRID;
        if (t + 1u == target) {
            __threadfence();
            g_gen = (unsigned)(b + 1);           // release
        } else {
            while (g_gen < (unsigned)(b + 1)) { } // spin (all blocks resident)
        }
        __threadfence();
    }
    __syncthreads();
}

__global__ __launch_bounds__(THREADS, 2) void sinkhorn_kernel() {
    const int tid  = threadIdx.x;
    const int lane = tid & 31;
    const int wid  = tid >> 5;

    __shared__ float part[MAXROWS][THREADS / 32];

    for (int phase = 0; phase < NPHASE; ++phase) {
        const int dir = phase & 1;   // 0: update u (rows=x, cols=y, w=v)
        const float*  __restrict__ rowp = g_pr[dir];
        const float*  __restrict__ rowq = g_qr[dir];
        const float2* __restrict__ colp = (const float2*)g_pr[dir ^ 1];
        const float2* __restrict__ colq = (const float2*)g_qr[dir ^ 1];
        const float2* __restrict__ wsrc = (const float2*)(dir ? g_u : g_v);
        float*        __restrict__ out  = dir ? g_v : g_u;

        // Per-thread slice of the reduce side: negated rotated coords (packed)
        // + scaled potentials (scalar halves). Coords are read-only (__ldg);
        // potentials were written by other SMs last phase -> must bypass L1.
        unsigned long long NP[PAIRS], NQ[PAIRS];
        float Wl[PAIRS], Wh[PAIRS];
#pragma unroll
        for (int k = 0; k < PAIRS; k++) {
            int idx = tid + k * THREADS;
            float2 cp = __ldg(&colp[idx]);
            float2 cq = __ldg(&colq[idx]);
            NP[k] = packf2(-cp.x, -cp.y);
            NQ[k] = packf2(-cq.x, -cq.y);
            float2 ww = __ldcg(&wsrc[idx]);
            Wl[k] = ww.x * KSCALE;
            Wh[k] = ww.y * KSCALE;
        }

        // Rows strided over blocks, processed 2 at a time for ILP.
        int r = 0;
        int i = blockIdx.x;
        for (; i + GRID < NPTS; i += 2 * GRID, r += 2) {
            float p0 = __ldg(rowp + i),        q0 = __ldg(rowq + i);
            float p1 = __ldg(rowp + i + GRID), q1 = __ldg(rowq + i + GRID);
            unsigned long long P0 = packf2(p0, p0), Q0 = packf2(q0, q0);
            unsigned long long P1 = packf2(p1, p1), Q1 = packf2(q1, q1);
            float a0 = 0.0f, b0 = 0.0f, a1 = 0.0f, b1 = 0.0f;
#pragma unroll
            for (int k = 0; k < PAIRS; k++) {
                unsigned long long e0 = addx2(P0, NP[k]);
                unsigned long long f0 = addx2(Q0, NQ[k]);
                unsigned long long e1 = addx2(P1, NP[k]);
                unsigned long long f1 = addx2(Q1, NQ[k]);
                float e0l, e0h, f0l, f0h, e1l, e1h, f1l, f1h;
                unpackf2(e0, e0l, e0h); unpackf2(f0, f0l, f0h);
                unpackf2(e1, e1l, e1h); unpackf2(f1, f1l, f1h);
                // FMNMX with |.| operand modifiers (alu pipe)
                float m0l = fmaxf(fabsf(e0l), fabsf(f0l));
                float m0h = fmaxf(fabsf(e0h), fabsf(f0h));
                float m1l = fmaxf(fabsf(e1l), fabsf(f1l));
                float m1h = fmaxf(fabsf(e1h), fabsf(f1h));
                a0 += ex2f(Wl[k] - m0l);
                b0 += ex2f(Wh[k] - m0h);
                a1 += ex2f(Wl[k] - m1l);
                b1 += ex2f(Wh[k] - m1h);
            }
            float s0 = a0 + b0;
            float s1 = a1 + b1;
#pragma unroll
            for (int o = 16; o; o >>= 1) {
                s0 += __shfl_xor_sync(0xffffffffu, s0, o);
                s1 += __shfl_xor_sync(0xffffffffu, s1, o);
            }
            if (lane == 0) { part[r][wid] = s0; part[r + 1][wid] = s1; }
        }
        // leftover single row (blocks with odd row count)
        for (; i < NPTS; i += GRID, r += 1) {
            float p0 = __ldg(rowp + i), q0 = __ldg(rowq + i);
            unsigned long long P0 = packf2(p0, p0), Q0 = packf2(q0, q0);
            float a0 = 0.0f, b0 = 0.0f;
#pragma unroll
            for (int k = 0; k < PAIRS; k++) {
                unsigned long long e0 = addx2(P0, NP[k]);
                unsigned long long f0 = addx2(Q0, NQ[k]);
                float e0l, e0h, f0l, f0h;
                unpackf2(e0, e0l, e0h); unpackf2(f0, f0l, f0h);
                float m0l = fmaxf(fabsf(e0l), fabsf(f0l));
                float m0h = fmaxf(fabsf(e0h), fabsf(f0h));
                a0 += ex2f(Wl[k] - m0l);
                b0 += ex2f(Wh[k] - m0h);
            }
            float s0 = a0 + b0;
#pragma unroll
            for (int o = 16; o; o >>= 1)
                s0 += __shfl_xor_sync(0xffffffffu, s0, o);
            if (lane == 0) part[r][wid] = s0;
        }
        const int nrows = r;

        __syncthreads();
        for (int rr = tid; rr < nrows; rr += THREADS) {
            float ss = 0.0f;
#pragma unroll
            for (int q = 0; q < THREADS / 32; q++) ss += part[rr][q];
            out[blockIdx.x + rr * GRID] = CONST_A - EPS_LN2 * lg2f(ss);
        }

        grid_barrier(phase);
    }
}

// Write pi and C, accumulate per-row cost partials (deterministic order).
#define FTHREADS 256
#define FJPT     16
__global__ __launch_bounds__(FTHREADS) void finalize_kernel(
    const float2* __restrict__ x, const float2* __restrict__ y,
    float* __restrict__ out) {
    __shared__ float red[FTHREADS / 32];
    const int i = blockIdx.x;
    const int tid = threadIdx.x;

    float2 xi = x[i];
    float ui = g_u[i];
    float* __restrict__ pi_out = out + 1;
    float* __restrict__ c_out  = out + 1 + (size_t)NPTS * NPTS;
    const size_t base = (size_t)i * NPTS;

    float acc = 0.0f;
#pragma unroll
    for (int k = 0; k < FJPT; k++) {
        int j = tid + k * FTHREADS;
        float2 yj = y[j];
        float c = fabsf(xi.x - yj.x) + fabsf(xi.y - yj.y);
        float p = ex2f((ui + g_v[j] - c) * KSCALE);
        pi_out[base + j] = p;
        c_out[base + j]  = c;
        acc += p * c;
    }
#pragma unroll
    for (int o = 16; o; o >>= 1)
        acc += __shfl_xor_sync(0xffffffffu, acc, o);
    if ((tid & 31) == 0) red[tid >> 5] = acc;
    __syncthreads();
    if (tid == 0) {
        float s = 0.0f;
#pragma unroll
        for (int q = 0; q < FTHREADS / 32; q++) s += red[q];
        g_part[i] = s;
    }
}

__global__ __launch_bounds__(FTHREADS) void cost_reduce(float* __restrict__ out) {
    __shared__ float red[FTHREADS / 32];
    const int tid = threadIdx.x;
    float s = 0.0f;
    for (int k = tid; k < NPTS; k += FTHREADS) s += g_part[k];
#pragma unroll
    for (int o = 16; o; o >>= 1)
        s += __shfl_xor_sync(0xffffffffu, s, o);
    if ((tid & 31) == 0) red[tid >> 5] = s;
    __syncthreads();
    if (tid == 0) {
        float t = 0.0f;
#pragma unroll
        for (int q = 0; q < FTHREADS / 32; q++) t += red[q];
        out[0] = t;   // P = 1 -> cost^(1/P) == cost
    }
}

extern "C" void kernel_launch(void* const* d_in, const int* in_sizes, int n_in,
                              void* d_out, int out_size) {
    const float2* x = (const float2*)d_in[0];
    const float2* y = (const float2*)d_in[1];
    float* out = (float*)d_out;

    init_kernel<<<NPTS / 256, 256>>>(x, y);
    sinkhorn_kernel<<<GRID, THREADS>>>();
    finalize_kernel<<<NPTS, FTHREADS>>>(x, y, out);
    cost_reduce<<<1, FTHREADS>>>(out);
    (void)in_sizes; (void)n_in; (void)out_size;
}